// round 15
// baseline (speedup 1.0000x reference)
#include <cuda_runtime.h>
#include <cuda_bf16.h>
#include <math.h>

// T=2048 tokens, H=2048 hidden, V=32000 vocab, E=16 experts, top-2.
// Inputs: hidden_states (T*H f32), gate_w (16*H f32), expert_biases (16*V f32).
// Output: bias (T*V f32) then aux_loss (1 f32).
//
// Fused kernel, 64-reg cap (launch_bounds(256,4)) so the gate path cannot
// inflate bias-block occupancy (the R13 failure). Gate blocks (bids 0..255,
// wave 1) finish 8 tokens each IN-WARP and bump per-group counters; bias
// blocks stage their 32KB expert chunk first, then spin (nanosleep) only on
// their own group's counter. Gate latency hides under bias stores.

#define NUM_E 16
#define MAX_T 8192
#define CHUNK_F4 128          // 512 floats = 2048 B per expert per chunk
#define TOK_GRP  128

__device__ float  g_probs[MAX_T * NUM_E];
__device__ float4 g_meta[MAX_T];            // (w0, w1, bitcast i0, bitcast i1)
__device__ int    g_grp_cnt[MAX_T / TOK_GRP];
__device__ int    g_tot_cnt;

// ---------------------------------------------------------------------------
__global__ void reset_kernel(int ngrp)
{
    if (threadIdx.x < ngrp) g_grp_cnt[threadIdx.x] = 0;
    if (threadIdx.x == 31)  g_tot_cnt = 0;
}

// ---------------------------------------------------------------------------
__global__ __launch_bounds__(256, 4) void fused_kernel(
    const float* __restrict__ hidden,
    const float* __restrict__ gate_w,
    const float* __restrict__ biases,
    float* __restrict__ out,
    float* __restrict__ out_aux,
    int H, int V, int T)
{
    __shared__ __align__(16) char smem_raw[34816 + 64];

    const int tid    = threadIdx.x;
    const int bid    = blockIdx.x;
    const int nbGate = T >> 3;             // 256
    const int lane   = tid & 31;
    const int warp   = tid >> 5;

    if (bid < nbGate) {
        // =================== GATE PATH (1 token/warp, ~44 regs) ============
        const int Hf4 = H >> 2;            // 512
        const int tok = bid * 8 + warp;

        const float4* __restrict__ gf4  = (const float4*)gate_w;
        const float4* __restrict__ hrow = (const float4*)hidden + (size_t)tok * Hf4;

        float acc[NUM_E];
        #pragma unroll
        for (int e = 0; e < NUM_E; e++) acc[e] = 0.0f;

        // 4 chunks; per chunk batch 4 independent h loads (MLP=4)
        #pragma unroll
        for (int c = 0; c < 4; c++) {
            float4 h[4];
            #pragma unroll
            for (int jj = 0; jj < 4; jj++)
                h[jj] = hrow[lane + (c * 4 + jj) * 32];

            #pragma unroll
            for (int jj = 0; jj < 4; jj++) {
                const int pos = lane + (c * 4 + jj) * 32;
                #pragma unroll
                for (int e = 0; e < NUM_E; e++) {
                    float4 g = __ldg(&gf4[(size_t)e * Hf4 + pos]);
                    acc[e] += h[jj].x*g.x + h[jj].y*g.y + h[jj].z*g.z + h[jj].w*g.w;
                }
            }
        }

        // full-warp butterfly: all lanes hold complete logits
        #pragma unroll
        for (int e = 0; e < NUM_E; e++) {
            float v = acc[e];
            #pragma unroll
            for (int s = 16; s > 0; s >>= 1)
                v += __shfl_xor_sync(0xffffffffu, v, s);
            acc[e] = v;
        }

        if (lane == 0) {
            float mx = -1e30f;
            #pragma unroll
            for (int e = 0; e < NUM_E; e++) mx = fmaxf(mx, acc[e]);
            float p[NUM_E];
            float sum = 0.0f;
            #pragma unroll
            for (int e = 0; e < NUM_E; e++) { p[e] = expf(acc[e] - mx); sum += p[e]; }
            float inv = 1.0f / sum;

            int   i0 = 0, i1 = -1;
            float p0 = -1.0f, p1 = -1.0f;
            float pr[NUM_E];
            #pragma unroll
            for (int e = 0; e < NUM_E; e++) {
                float pe = p[e] * inv;
                pr[e] = pe;
                if (pe > p0)      { p1 = p0; i1 = i0; p0 = pe; i0 = e; }
                else if (pe > p1) { p1 = pe; i1 = e; }
            }
            float4* probs4 = (float4*)&g_probs[(size_t)tok * NUM_E];
            #pragma unroll
            for (int c = 0; c < 4; c++)
                probs4[c] = make_float4(pr[c*4], pr[c*4+1], pr[c*4+2], pr[c*4+3]);

            float s2 = p0 + p1;
            float4 m;
            m.x = p0 / s2;
            m.y = p1 / s2;
            m.z = __int_as_float(i0);
            m.w = __int_as_float(i1);
            g_meta[tok] = m;
        }

        __syncthreads();
        if (tid == 0) {
            __threadfence();
            atomicAdd(&g_grp_cnt[bid >> 4], 1);   // 16 gate blocks per group
            atomicAdd(&g_tot_cnt, 1);
        }
        return;
    }

    // =================== BIAS PATH (48 regs) ===============================
    float4 (*sB)[CHUNK_F4] = (float4 (*)[CHUNK_F4])smem_raw;        // 32 KB
    float4* smeta = (float4*)(smem_raw + 32768);                    // 2 KB

    const int nchunks = (V / 4 + CHUNK_F4 - 1) / CHUNK_F4;   // 63
    const int i     = bid - nbGate;
    const int bx    = i % nchunks;                 // v-chunk
    const int by    = i / nchunks;                 // token group
    const int Vf4   = V >> 2;                      // 8000
    const int vbase = bx * CHUNK_F4;               // 2048B-aligned
    const int clen  = min(CHUNK_F4, Vf4 - vbase);  // 128 or 64 (tail)
    const int tbase = by * TOK_GRP;

    const float4* __restrict__ bf4 = (const float4*)biases;
    float4* __restrict__ of4 = (float4*)out;

    // stage sB — independent of gating, overlaps the gate wave
    for (int k = tid; k < NUM_E * CHUNK_F4; k += 256) {
        int e = k >> 7, p = k & (CHUNK_F4 - 1);
        if (p < clen) sB[e][p] = bf4[(size_t)e * Vf4 + vbase + p];
    }

    // wait only for this token group's 16 gate blocks
    if (tid == 0) {
        while (atomicAdd(&g_grp_cnt[by], 0) < 16) __nanosleep(64);
        __threadfence();
    }
    __syncthreads();

    if (tid < TOK_GRP) smeta[tid] = g_meta[tbase + tid];
    __syncthreads();

    // warp-per-token, lane-contiguous 16B streaming stores
    for (int t = warp; t < TOK_GRP; t += 8) {
        float4 m = smeta[t];
        const float w0 = m.x, w1 = m.y;
        const int i0 = __float_as_int(m.z);
        const int i1 = __float_as_int(m.w);
        float4* __restrict__ orow = &of4[(size_t)(tbase + t) * Vf4 + vbase];
        #pragma unroll 4
        for (int p = lane; p < clen; p += 32) {
            float4 a = sB[i0][p];
            float4 b = sB[i1][p];
            float4 r;
            r.x = w0 * a.x + w1 * b.x;
            r.y = w0 * a.y + w1 * b.y;
            r.z = w0 * a.z + w1 * b.z;
            r.w = w0 * a.w + w1 * b.w;
            __stcs(&orow[p], r);
        }
    }

    // ---- aux loss: first bias block, after all gating done ----
    if (i == 0) {
        if (tid == 0) {
            while (atomicAdd(&g_tot_cnt, 0) < nbGate) __nanosleep(64);
            __threadfence();
        }
        __syncthreads();                       // also: sB reads all done

        float4* s4  = &sB[0][0];               // reuse sB as scratch
        float4* su4 = &sB[4][0];

        const int e4 = tid & 3;
        const int c  = tid >> 2;
        const float4* __restrict__ probs4 = (const float4*)g_probs;

        float4 sum = make_float4(0.f, 0.f, 0.f, 0.f);
        for (int t = c; t < T; t += 64) {
            float4 v = probs4[(size_t)t * 4 + e4];
            sum.x += v.x; sum.y += v.y; sum.z += v.z; sum.w += v.w;
        }
        s4[tid] = sum;
        __syncthreads();

        if (tid < 4) {
            float4 u = make_float4(0.f, 0.f, 0.f, 0.f);
            #pragma unroll
            for (int cc = 0; cc < 64; cc++) {
                float4 v = s4[cc * 4 + tid];
                u.x += v.x; u.y += v.y; u.z += v.z; u.w += v.w;
            }
            su4[tid] = u;
        }
        __syncthreads();

        if (tid == 0) {
            float invT = 1.0f / (float)T;
            float aux = 0.0f;
            #pragma unroll
            for (int q = 0; q < 4; q++) {
                float4 u = su4[q];
                float a = u.x * invT, b = u.y * invT;
                float cc = u.z * invT, d = u.w * invT;
                aux += a * logf(a) + b * logf(b) + cc * logf(cc) + d * logf(d);
            }
            out_aux[0] = aux * (float)NUM_E;
        }
    }
}

// ---------------------------------------------------------------------------
extern "C" void kernel_launch(void* const* d_in, const int* in_sizes, int n_in,
                              void* d_out, int out_size)
{
    const float* hidden = (const float*)d_in[0];
    const float* gate_w = (const float*)d_in[1];
    const float* biases = (const float*)d_in[2];
    float* out = (float*)d_out;

    const int H = in_sizes[1] / NUM_E;         // 2048
    const int T = in_sizes[0] / H;             // 2048
    const int V = in_sizes[2] / NUM_E;         // 32000

    const int nbGate  = T / 8;                             // 256
    const int nchunks = (V / 4 + CHUNK_F4 - 1) / CHUNK_F4; // 63
    const int ngrp    = T / TOK_GRP;                       // 16

    reset_kernel<<<1, 32>>>(ngrp);
    fused_kernel<<<nbGate + nchunks * ngrp, 256>>>(
        hidden, gate_w, biases, out, out + (size_t)T * V, H, V, T);
}